// round 15
// baseline (speedup 1.0000x reference)
#include <cuda_runtime.h>
#include <cuda_bf16.h>
#include <cstdint>
#include <cmath>

// ============================================================================
// Inputs: f32 (bf16-valued, widened by harness). K=2048, R=32768.
// Output mode 0: fp32 concat [q_as_f32 (R*K) | scale (R)].
//
// R14: 723.7us fused GEMM @ tensor=62.5%; consumer warps' issue stream mixes
// cp.async + addressing with LDSM/MMA. R15: warp specialization — warp 4 is
// a dedicated cp.async producer; warps 0-3 are pure LDSM/MMA consumers
// (64x64 tiles, A frags double-buffered, B single-buffered to fit 204 regs).
// ============================================================================

__device__ __nv_bfloat16 g_xb[(size_t)67108864];        // 134 MB x as bf16
__device__ __nv_bfloat16 g_ht[(size_t)2048 * 2048];     // 8 MB h^T as bf16
__device__ float        g_y[(size_t)67108864];          // fallback (mode!=0)
__device__ unsigned     g_absmax[32768];                // per-row absmax bits
__device__ unsigned     g_cnt[1024];                    // per-m-slab arrivals

static constexpr int MT = 128, NT = 128, KC = 64, STAGES = 3;
static constexpr int THREADS = 160;                     // 4 consumer + 1 producer
static constexpr int A_STAGE_BYTES = MT * KC * 2;           // 16384
static constexpr int B_STAGE_BYTES = NT * KC * 2;           // 16384
static constexpr int SMEM_B_BASE = STAGES * A_STAGE_BYTES;  // 49152
static constexpr int SMEM_TOTAL = STAGES * (A_STAGE_BYTES + B_STAGE_BYTES); // 98304

__device__ __forceinline__ uint32_t smem_u32(const void* p) {
    uint32_t a;
    asm("{ .reg .u64 t; cvta.to.shared.u64 t, %1; cvt.u32.u64 %0, t; }"
        : "=r"(a) : "l"(p));
    return a;
}
__device__ __forceinline__ uint32_t swz(uint32_t off) {
    return off ^ ((off >> 3) & 0x70u);
}
__device__ __forceinline__ void cp_async16(uint32_t s_addr, const void* g_addr) {
    asm volatile("cp.async.cg.shared.global [%0], [%1], 16;"
                 :: "r"(s_addr), "l"(g_addr) : "memory");
}
#define CP_COMMIT() asm volatile("cp.async.commit_group;" ::: "memory")
#define CP_WAIT(n)  asm volatile("cp.async.wait_group %0;" :: "n"(n) : "memory")

__device__ __forceinline__ void ldmatrix_x4(uint32_t* r, uint32_t addr) {
    asm volatile("ldmatrix.sync.aligned.m8n8.x4.shared.b16 {%0,%1,%2,%3}, [%4];"
                 : "=r"(r[0]), "=r"(r[1]), "=r"(r[2]), "=r"(r[3]) : "r"(addr));
}
__device__ __forceinline__ void mma_16816(float* d, const uint32_t* a,
                                          uint32_t b0, uint32_t b1) {
    asm volatile(
        "mma.sync.aligned.m16n8k16.row.col.f32.bf16.bf16.f32 "
        "{%0,%1,%2,%3}, {%4,%5,%6,%7}, {%8,%9}, {%0,%1,%2,%3};"
        : "+f"(d[0]), "+f"(d[1]), "+f"(d[2]), "+f"(d[3])
        : "r"(a[0]), "r"(a[1]), "r"(a[2]), "r"(a[3]), "r"(b0), "r"(b1));
}

__global__ void zero_meta_kernel(int R) {
    int i = blockIdx.x * blockDim.x + threadIdx.x;
    if (i < R) g_absmax[i] = 0u;
    if (i < 1024) g_cnt[i] = 0u;
}

__global__ void __launch_bounds__(256) convert_x_kernel(
    const float4* __restrict__ xf, long long n4) {
    long long i = (long long)blockIdx.x * blockDim.x + threadIdx.x;
    long long base = i * 2;
    if (base + 1 < n4) {
        float4 v0 = xf[base + 0];
        float4 v1 = xf[base + 1];
        __nv_bfloat16 o[8] = {
            __float2bfloat16(v0.x), __float2bfloat16(v0.y),
            __float2bfloat16(v0.z), __float2bfloat16(v0.w),
            __float2bfloat16(v1.x), __float2bfloat16(v1.y),
            __float2bfloat16(v1.z), __float2bfloat16(v1.w)};
        *reinterpret_cast<uint4*>(&g_xb[base * 4]) =
            *reinterpret_cast<const uint4*>(o);
    }
}

__global__ void transpose_h_kernel(const float* __restrict__ h, int K) {
    __shared__ float tile[32][33];
    int x = blockIdx.x * 32 + threadIdx.x;
    int y = blockIdx.y * 32 + threadIdx.y;
#pragma unroll
    for (int j = 0; j < 32; j += 8)
        tile[threadIdx.y + j][threadIdx.x] = h[(size_t)(y + j) * K + x];
    __syncthreads();
    int xo = blockIdx.y * 32 + threadIdx.x;
    int yo = blockIdx.x * 32 + threadIdx.y;
#pragma unroll
    for (int j = 0; j < 32; j += 8)
        g_ht[(size_t)(yo + j) * K + xo] =
            __float2bfloat16(tile[threadIdx.x][threadIdx.y + j]);
}

// ============================================================================
// Warp-specialized GEMM + fused absmax + cross-CTA quant epilogue.
// Warps 0-3: consumers (2x2 grid, 64x64 tiles). Warp 4: cp.async producer.
// ============================================================================
__global__ void __launch_bounds__(THREADS, 2) gemm_fused_kernel(
    void* __restrict__ d_out, int K, long long R, int mode) {
    extern __shared__ char smem[];
    const uint32_t smem_base = smem_u32(smem);
    const int tid = threadIdx.x;
    const int wid = tid >> 5;
    const int lane = tid & 31;

    const int m0 = blockIdx.y * MT;
    const int n0 = blockIdx.x * NT;
    const int NCHUNK = K / KC;   // 32

    if (wid == 4) {
        // ------------------- PRODUCER WARP -------------------
        // lane covers rows lane*4..lane*4+3, cols 0..7 for both A and B.
        const int row0 = lane * 4;
        const __nv_bfloat16* Ag = g_xb + (size_t)(m0 + row0) * K;
        const __nv_bfloat16* Bg = g_ht + (size_t)(n0 + row0) * K;

        // prologue: stages 0..1
#pragma unroll
        for (int s = 0; s < STAGES - 1; s++) {
            uint32_t sA = smem_base + s * A_STAGE_BYTES;
            uint32_t sB = smem_base + SMEM_B_BASE + s * B_STAGE_BYTES;
#pragma unroll
            for (int r = 0; r < 4; r++) {
                uint32_t ro = (uint32_t)(row0 + r) * 128u;
                const __nv_bfloat16* ga = Ag + (size_t)r * K + s * KC;
                const __nv_bfloat16* gb = Bg + (size_t)r * K + s * KC;
#pragma unroll
                for (int c = 0; c < 8; c++) {
                    uint32_t so = swz(ro + c * 16u);
                    cp_async16(sA + so, ga + c * 8);
                    cp_async16(sB + so, gb + c * 8);
                }
            }
            CP_COMMIT();
        }

        for (int kc = 0; kc < NCHUNK; kc++) {
            CP_WAIT(STAGES - 2);
            __syncthreads();            // (1) barrier shared with consumers
            const bool do_load = (kc + STAGES - 1) < NCHUNK;
            if (do_load) {
                const int wst = (kc + STAGES - 1) % STAGES;
                const int kb = (kc + STAGES - 1) * KC;
                uint32_t sA = smem_base + wst * A_STAGE_BYTES;
                uint32_t sB = smem_base + SMEM_B_BASE + wst * B_STAGE_BYTES;
#pragma unroll
                for (int r = 0; r < 4; r++) {
                    uint32_t ro = (uint32_t)(row0 + r) * 128u;
                    const __nv_bfloat16* ga = Ag + (size_t)r * K + kb;
                    const __nv_bfloat16* gb = Bg + (size_t)r * K + kb;
#pragma unroll
                    for (int c = 0; c < 8; c++) {
                        uint32_t so = swz(ro + c * 16u);
                        cp_async16(sA + so, ga + c * 8);
                        cp_async16(sB + so, gb + c * 8);
                    }
                }
            }
            CP_COMMIT();
        }

        // epilogue participation: barriers only
        __syncthreads();                // (2) matches consumers post-absmax
        if (mode != 0) return;
        __syncthreads();                // (3) rendezvous barrier
        return;
    }

    // ------------------- CONSUMER WARPS (0-3) -------------------
    const int wm = wid >> 1;
    const int wn = wid & 1;
    const int lrow = lane & 15;
    const int lkb  = (lane >> 4) * 8;

    uint32_t araw[4], braw[4];
#pragma unroll
    for (int mi = 0; mi < 4; mi++)
        araw[mi] = (uint32_t)(wm * 64 + mi * 16 + lrow) * 128u +
                   (uint32_t)lkb * 2u;
#pragma unroll
    for (int nj = 0; nj < 4; nj++)
        braw[nj] = (uint32_t)(wn * 64 + nj * 16 + lrow) * 128u +
                   (uint32_t)lkb * 2u;

    float d[4][8][4];
#pragma unroll
    for (int mi = 0; mi < 4; mi++)
#pragma unroll
        for (int ni = 0; ni < 8; ni++)
#pragma unroll
            for (int j = 0; j < 4; j++) d[mi][ni][j] = 0.0f;

    for (int kc = 0; kc < NCHUNK; kc++) {
        __syncthreads();                // (1) data for chunk kc now visible

        const int st = kc % STAGES;
        const uint32_t sA = smem_base + st * A_STAGE_BYTES;
        const uint32_t sB = smem_base + SMEM_B_BASE + st * B_STAGE_BYTES;

        uint32_t a[2][4][4], b[4][4];
        // step-0 A fragments
#pragma unroll
        for (int mi = 0; mi < 4; mi++)
            ldmatrix_x4(a[0][mi], sA + swz(araw[mi]));

#pragma unroll
        for (int s = 0; s < KC / 16; s++) {
            const int cur = s & 1;
            const int nxt = cur ^ 1;
            const uint32_t so = (uint32_t)s * 32u;
            // B fragments for this step (single-buffered)
#pragma unroll
            for (int nj = 0; nj < 4; nj++)
                ldmatrix_x4(b[nj], sB + swz(braw[nj] + so));
            // A prefetch for next step (covers B ldsm latency)
            if (s < KC / 16 - 1) {
#pragma unroll
                for (int mi = 0; mi < 4; mi++)
                    ldmatrix_x4(a[nxt][mi], sA + swz(araw[mi] + so + 32u));
            }
#pragma unroll
            for (int mi = 0; mi < 4; mi++)
#pragma unroll
                for (int nj = 0; nj < 4; nj++) {
                    mma_16816(d[mi][2 * nj + 0], a[cur][mi], b[nj][0], b[nj][2]);
                    mma_16816(d[mi][2 * nj + 1], a[cur][mi], b[nj][1], b[nj][3]);
                }
        }
    }

    // ---- epilogue phase 1: row absmax + atomicMax ----
    const int g = lane >> 2;
    const int tc = (lane & 3) * 2;
#pragma unroll
    for (int mi = 0; mi < 4; mi++) {
#pragma unroll
        for (int half = 0; half < 2; half++) {
            int r = m0 + wm * 64 + mi * 16 + half * 8 + g;
            float mx = 0.0f;
#pragma unroll
            for (int ni = 0; ni < 8; ni++)
                mx = fmaxf(mx, fmaxf(fabsf(d[mi][ni][half * 2 + 0]),
                                     fabsf(d[mi][ni][half * 2 + 1])));
            mx = fmaxf(mx, __shfl_xor_sync(0xFFFFFFFFu, mx, 1));
            mx = fmaxf(mx, __shfl_xor_sync(0xFFFFFFFFu, mx, 2));
            if ((lane & 3) == 0)
                atomicMax(&g_absmax[r], __float_as_uint(mx));
        }
    }

    __syncthreads();                    // (2) all maxes issued
    if (mode != 0) {
#pragma unroll
        for (int mi = 0; mi < 4; mi++)
#pragma unroll
            for (int half = 0; half < 2; half++) {
                int r = m0 + wm * 64 + mi * 16 + half * 8 + g;
                float* yrow = g_y + (size_t)r * K + n0 + wn * 64;
#pragma unroll
                for (int ni = 0; ni < 8; ni++)
                    *reinterpret_cast<float2*>(yrow + ni * 8 + tc) =
                        make_float2(d[mi][ni][half * 2 + 0],
                                    d[mi][ni][half * 2 + 1]);
            }
        return;
    }

    // ---- epilogue phase 2: slab rendezvous ----
    if (tid == 0) {
        __threadfence();
        atomicAdd(&g_cnt[blockIdx.y], 1u);
        unsigned target = gridDim.x;
        unsigned v;
        do {
            asm volatile("ld.acquire.gpu.global.u32 %0, [%1];"
                         : "=r"(v) : "l"(&g_cnt[blockIdx.y]));
        } while (v < target);
    }
    __syncthreads();                    // (3) absmax final

    // ---- epilogue phase 3: quantize register tile -> d_out ----
    float* outq = reinterpret_cast<float*>(d_out);
    const long long qelems = R * (long long)K;
#pragma unroll
    for (int mi = 0; mi < 4; mi++) {
#pragma unroll
        for (int half = 0; half < 2; half++) {
            int r = m0 + wm * 64 + mi * 16 + half * 8 + g;
            unsigned ab;
            asm volatile("ld.global.cg.u32 %0, [%1];"
                         : "=r"(ab) : "l"(&g_absmax[r]));
            const float amax = __uint_as_float(ab);
            const float scale = amax / 127.0f;
            const float inv = (scale == 0.0f) ? 1.0f : (1.0f / scale);
            float* qrow = outq + (size_t)r * K + n0 + wn * 64;
#pragma unroll
            for (int ni = 0; ni < 8; ni++) {
                float q0 = rintf(d[mi][ni][half * 2 + 0] * inv);
                float q1 = rintf(d[mi][ni][half * 2 + 1] * inv);
                q0 = fminf(fmaxf(q0, -127.0f), 127.0f);
                q1 = fminf(fmaxf(q1, -127.0f), 127.0f);
                *reinterpret_cast<float2*>(qrow + ni * 8 + tc) =
                    make_float2(q0, q1);
            }
        }
    }
    if (blockIdx.x == 0) {
        int r = m0 + tid;               // tid 0..127 (consumers only here)
        unsigned ab;
        asm volatile("ld.global.cg.u32 %0, [%1];"
                     : "=r"(ab) : "l"(&g_absmax[r]));
        outq[qelems + r] = __uint_as_float(ab) / 127.0f;
    }
}

// ============================================================================
// quantize fallback for modes 1/2
// ============================================================================
__global__ void __launch_bounds__(256) quant_kernel(void* __restrict__ d_out,
                                                    int K, long long R, int mode) {
    const int r = blockIdx.x;
    const int tid = threadIdx.x;
    const float amax = __uint_as_float(g_absmax[r]);
    const float scale = amax / 127.0f;
    const float safe = (scale == 0.0f) ? 1.0f : scale;
    const float inv = 1.0f / safe;

    const float4* yrow = reinterpret_cast<const float4*>(g_y + (size_t)r * K);
    const long long qelems = R * (long long)K;

    for (int i = tid; i < K / 4; i += 256) {
        float4 v = yrow[i];
        float vals[4] = {v.x, v.y, v.z, v.w};
        int q[4];
#pragma unroll
        for (int j = 0; j < 4; j++) {
            float t = rintf(vals[j] * inv);
            q[j] = (int)fminf(fmaxf(t, -127.0f), 127.0f);
        }
        uint32_t p = (uint32_t)(q[0] & 0xFF) | ((uint32_t)(q[1] & 0xFF) << 8) |
                     ((uint32_t)(q[2] & 0xFF) << 16) | ((uint32_t)(q[3] & 0xFF) << 24);
        reinterpret_cast<uint32_t*>(
            reinterpret_cast<char*>(d_out) + (size_t)r * K)[i] = p;
    }
    if (tid == 0 && mode == 1) {
        float* sc = reinterpret_cast<float*>(
            reinterpret_cast<char*>(d_out) + qelems);
        sc[r] = scale;
    }
}

// ============================================================================
// launcher (graph-capture clean)
// ============================================================================
static int isqrt_ll(long long v) {
    long long r = (long long)sqrt((double)v);
    while (r * r > v) r--;
    while ((r + 1) * (r + 1) <= v) r++;
    return (int)r;
}

extern "C" void kernel_launch(void* const* d_in, const int* in_sizes, int n_in,
                              void* d_out, int out_size) {
    long long s0 = in_sizes[0], s1 = (n_in > 1) ? in_sizes[1] : 0;
    const void* xv; const void* hv;
    long long numel_x, numel_h;
    if (s0 >= s1) { xv = d_in[0]; numel_x = s0; hv = d_in[1]; numel_h = s1; }
    else          { xv = d_in[1]; numel_x = s1; hv = d_in[0]; numel_h = s0; }
    const int K = isqrt_ll(numel_h);        // 2048
    const long long R = numel_x / K;        // 32768
    const long long qelems = R * (long long)K;

    int mode;
    if ((long long)out_size == qelems + R)            mode = 0;
    else if ((long long)out_size == qelems + 4LL * R) mode = 1;
    else                                              mode = 2;

    cudaFuncSetAttribute(gemm_fused_kernel,
                         cudaFuncAttributeMaxDynamicSharedMemorySize, SMEM_TOTAL);

    zero_meta_kernel<<<(unsigned)((R + 255) / 256), 256>>>((int)R);
    convert_x_kernel<<<(unsigned)((numel_x / 8 + 255) / 256), 256>>>(
        (const float4*)xv, numel_x / 4);
    transpose_h_kernel<<<dim3(K / 32, K / 32), dim3(32, 8)>>>((const float*)hv, K);
    gemm_fused_kernel<<<dim3(K / NT, (unsigned)(R / MT)), THREADS, SMEM_TOTAL>>>(
        d_out, K, R, mode);
    if (mode != 0)
        quant_kernel<<<(unsigned)R, 256>>>(d_out, K, R, mode);
}

// round 16
// speedup vs baseline: 2.1697x; 2.1697x over previous
#include <cuda_runtime.h>
#include <cuda_bf16.h>
#include <cstdint>
#include <cmath>

// ============================================================================
// Inputs: f32 (bf16-valued, widened by harness). K=2048, R=32768.
// Output mode 0: fp32 concat [q_as_f32 (R*K) | scale (R)].
//
// R15 (warp specialization) regressed 2.2x: one producer warp = 64 LDGSTS x
// 8cyc serialized per chunk -> pipeline governor. R16 reverts to the proven
// R14 design (723.7us fused GEMM, 789.4 total): 128x128 CTA, 4 warps, 64x64
// warp tiles, 3-stage distributed cp.async, fragment double-buffering,
// fused cross-CTA quant epilogue. Micro: zero_meta folded into convert.
// Measured floor analysis: mainloop 686 + qwrite 34 + prep 66 ~= 786us.
// ============================================================================

__device__ __nv_bfloat16 g_xb[(size_t)67108864];        // 134 MB x as bf16
__device__ __nv_bfloat16 g_ht[(size_t)2048 * 2048];     // 8 MB h^T as bf16
__device__ float        g_y[(size_t)67108864];          // fallback (mode!=0)
__device__ unsigned     g_absmax[32768];                // per-row absmax bits
__device__ unsigned     g_cnt[1024];                    // per-m-slab arrivals

static constexpr int MT = 128, NT = 128, KC = 64, STAGES = 3;
static constexpr int THREADS = 128;
static constexpr int A_STAGE_BYTES = MT * KC * 2;           // 16384
static constexpr int B_STAGE_BYTES = NT * KC * 2;           // 16384
static constexpr int SMEM_B_BASE = STAGES * A_STAGE_BYTES;  // 49152
static constexpr int SMEM_TOTAL = STAGES * (A_STAGE_BYTES + B_STAGE_BYTES); // 98304

__device__ __forceinline__ uint32_t smem_u32(const void* p) {
    uint32_t a;
    asm("{ .reg .u64 t; cvta.to.shared.u64 t, %1; cvt.u32.u64 %0, t; }"
        : "=r"(a) : "l"(p));
    return a;
}
__device__ __forceinline__ uint32_t swz(uint32_t off) {
    return off ^ ((off >> 3) & 0x70u);
}
__device__ __forceinline__ void cp_async16(uint32_t s_addr, const void* g_addr) {
    asm volatile("cp.async.cg.shared.global [%0], [%1], 16;"
                 :: "r"(s_addr), "l"(g_addr) : "memory");
}
#define CP_COMMIT() asm volatile("cp.async.commit_group;" ::: "memory")
#define CP_WAIT(n)  asm volatile("cp.async.wait_group %0;" :: "n"(n) : "memory")

__device__ __forceinline__ void ldmatrix_x4(uint32_t* r, uint32_t addr) {
    asm volatile("ldmatrix.sync.aligned.m8n8.x4.shared.b16 {%0,%1,%2,%3}, [%4];"
                 : "=r"(r[0]), "=r"(r[1]), "=r"(r[2]), "=r"(r[3]) : "r"(addr));
}
__device__ __forceinline__ void mma_16816(float* d, const uint32_t* a,
                                          uint32_t b0, uint32_t b1) {
    asm volatile(
        "mma.sync.aligned.m16n8k16.row.col.f32.bf16.bf16.f32 "
        "{%0,%1,%2,%3}, {%4,%5,%6,%7}, {%8,%9}, {%0,%1,%2,%3};"
        : "+f"(d[0]), "+f"(d[1]), "+f"(d[2]), "+f"(d[3])
        : "r"(a[0]), "r"(a[1]), "r"(a[2]), "r"(a[3]), "r"(b0), "r"(b1));
}

// ============================================================================
// convert x (f32->bf16) + zero absmax/counters (folded; one launch)
// ============================================================================
__global__ void __launch_bounds__(256) convert_x_kernel(
    const float4* __restrict__ xf, long long n4, int R) {
    long long i = (long long)blockIdx.x * blockDim.x + threadIdx.x;
    // fold meta zeroing into the first blocks
    if (i < R) g_absmax[i] = 0u;
    if (i < 1024) g_cnt[i] = 0u;
    long long base = i * 2;
    if (base + 1 < n4) {
        float4 v0 = xf[base + 0];
        float4 v1 = xf[base + 1];
        __nv_bfloat16 o[8] = {
            __float2bfloat16(v0.x), __float2bfloat16(v0.y),
            __float2bfloat16(v0.z), __float2bfloat16(v0.w),
            __float2bfloat16(v1.x), __float2bfloat16(v1.y),
            __float2bfloat16(v1.z), __float2bfloat16(v1.w)};
        *reinterpret_cast<uint4*>(&g_xb[base * 4]) =
            *reinterpret_cast<const uint4*>(o);
    }
}

__global__ void transpose_h_kernel(const float* __restrict__ h, int K) {
    __shared__ float tile[32][33];
    int x = blockIdx.x * 32 + threadIdx.x;
    int y = blockIdx.y * 32 + threadIdx.y;
#pragma unroll
    for (int j = 0; j < 32; j += 8)
        tile[threadIdx.y + j][threadIdx.x] = h[(size_t)(y + j) * K + x];
    __syncthreads();
    int xo = blockIdx.y * 32 + threadIdx.x;
    int yo = blockIdx.x * 32 + threadIdx.y;
#pragma unroll
    for (int j = 0; j < 32; j += 8)
        g_ht[(size_t)(yo + j) * K + xo] =
            __float2bfloat16(tile[threadIdx.x][threadIdx.y + j]);
}

// ============================================================================
// GEMM + fused absmax + fused cross-CTA quantization epilogue (R14 design).
// 4 warps = 2(M) x 2(N), warp tile 64x64, 2 CTAs/SM, 3-stage pipeline.
// ============================================================================
__global__ void __launch_bounds__(THREADS, 2) gemm_fused_kernel(
    void* __restrict__ d_out, int K, long long R, int mode) {
    extern __shared__ char smem[];
    const uint32_t smem_base = smem_u32(smem);
    const int tid = threadIdx.x;
    const int wid = tid >> 5;
    const int lane = tid & 31;
    const int wm = wid >> 1;
    const int wn = wid & 1;

    const int m0 = blockIdx.y * MT;
    const int n0 = blockIdx.x * NT;

    const int lrow0 = tid >> 3;
    const int lcol  = tid & 7;
    const uint32_t soff0 = swz((uint32_t)lrow0 * 128u + (uint32_t)lcol * 16u);
    const size_t stride16 = (size_t)16 * K;
    const __nv_bfloat16* Aptr = g_xb + (size_t)(m0 + lrow0) * K + lcol * 8;
    const __nv_bfloat16* Bptr = g_ht + (size_t)(n0 + lrow0) * K + lcol * 8;

    const int lrow = lane & 15;
    const int lkb  = (lane >> 4) * 8;
    uint32_t araw[4], braw[4];
#pragma unroll
    for (int mi = 0; mi < 4; mi++)
        araw[mi] = (uint32_t)(wm * 64 + mi * 16 + lrow) * 128u +
                   (uint32_t)lkb * 2u;
#pragma unroll
    for (int nj = 0; nj < 4; nj++)
        braw[nj] = (uint32_t)(wn * 64 + nj * 16 + lrow) * 128u +
                   (uint32_t)lkb * 2u;

    float d[4][8][4];
#pragma unroll
    for (int mi = 0; mi < 4; mi++)
#pragma unroll
        for (int ni = 0; ni < 8; ni++)
#pragma unroll
            for (int j = 0; j < 4; j++) d[mi][ni][j] = 0.0f;

#pragma unroll
    for (int s = 0; s < STAGES - 1; s++) {
        uint32_t sA = smem_base + s * A_STAGE_BYTES;
        uint32_t sB = smem_base + SMEM_B_BASE + s * B_STAGE_BYTES;
#pragma unroll
        for (int i = 0; i < 8; i++)
            cp_async16(sA + soff0 + i * 2048u, Aptr + s * KC + i * stride16);
#pragma unroll
        for (int i = 0; i < 8; i++)
            cp_async16(sB + soff0 + i * 2048u, Bptr + s * KC + i * stride16);
        CP_COMMIT();
    }

    const int NCHUNK = K / KC;

    for (int kc = 0; kc < NCHUNK; kc++) {
        CP_WAIT(STAGES - 2);
        __syncthreads();

        const bool do_load = (kc + STAGES - 1) < NCHUNK;
        const int wst = (kc + STAGES - 1) % STAGES;
        const uint32_t wA = smem_base + wst * A_STAGE_BYTES;
        const uint32_t wB = smem_base + SMEM_B_BASE + wst * B_STAGE_BYTES;
        const int kb_next = (kc + STAGES - 1) * KC;

        const int st = kc % STAGES;
        const uint32_t sA = smem_base + st * A_STAGE_BYTES;
        const uint32_t sB = smem_base + SMEM_B_BASE + st * B_STAGE_BYTES;

        uint32_t a[2][4][4], b[2][4][4];
#pragma unroll
        for (int mi = 0; mi < 4; mi++)
            ldmatrix_x4(a[0][mi], sA + swz(araw[mi]));
#pragma unroll
        for (int nj = 0; nj < 4; nj++)
            ldmatrix_x4(b[0][nj], sB + swz(braw[nj]));

#pragma unroll
        for (int s = 0; s < KC / 16; s++) {
            const int cur = s & 1;
            const int nxt = cur ^ 1;
            if (s < KC / 16 - 1) {
                uint32_t so = (uint32_t)(s + 1) * 32u;
#pragma unroll
                for (int mi = 0; mi < 4; mi++)
                    ldmatrix_x4(a[nxt][mi], sA + swz(araw[mi] + so));
#pragma unroll
                for (int nj = 0; nj < 4; nj++)
                    ldmatrix_x4(b[nxt][nj], sB + swz(braw[nj] + so));
            }
            if (do_load) {
#pragma unroll
                for (int j = 0; j < 4; j++) {
                    int i = s * 4 + j;
                    uint32_t dst = (i < 8 ? wA : wB) + soff0 + (i & 7) * 2048u;
                    const __nv_bfloat16* src =
                        (i < 8 ? Aptr : Bptr) + kb_next + (i & 7) * stride16;
                    cp_async16(dst, src);
                }
            }
#pragma unroll
            for (int mi = 0; mi < 4; mi++)
#pragma unroll
                for (int nj = 0; nj < 4; nj++) {
                    mma_16816(d[mi][2 * nj + 0], a[cur][mi],
                              b[cur][nj][0], b[cur][nj][2]);
                    mma_16816(d[mi][2 * nj + 1], a[cur][mi],
                              b[cur][nj][1], b[cur][nj][3]);
                }
        }
        CP_COMMIT();
    }

    // ---- epilogue phase 1: row absmax + atomicMax ----
    const int g = lane >> 2;
    const int tc = (lane & 3) * 2;
#pragma unroll
    for (int mi = 0; mi < 4; mi++) {
#pragma unroll
        for (int half = 0; half < 2; half++) {
            int r = m0 + wm * 64 + mi * 16 + half * 8 + g;
            float mx = 0.0f;
#pragma unroll
            for (int ni = 0; ni < 8; ni++)
                mx = fmaxf(mx, fmaxf(fabsf(d[mi][ni][half * 2 + 0]),
                                     fabsf(d[mi][ni][half * 2 + 1])));
            mx = fmaxf(mx, __shfl_xor_sync(0xFFFFFFFFu, mx, 1));
            mx = fmaxf(mx, __shfl_xor_sync(0xFFFFFFFFu, mx, 2));
            if ((lane & 3) == 0)
                atomicMax(&g_absmax[r], __float_as_uint(mx));
        }
    }

    if (mode != 0) {
#pragma unroll
        for (int mi = 0; mi < 4; mi++)
#pragma unroll
            for (int half = 0; half < 2; half++) {
                int r = m0 + wm * 64 + mi * 16 + half * 8 + g;
                float* yrow = g_y + (size_t)r * K + n0 + wn * 64;
#pragma unroll
                for (int ni = 0; ni < 8; ni++)
                    *reinterpret_cast<float2*>(yrow + ni * 8 + tc) =
                        make_float2(d[mi][ni][half * 2 + 0],
                                    d[mi][ni][half * 2 + 1]);
            }
        return;
    }

    // ---- epilogue phase 2: slab rendezvous ----
    __syncthreads();
    if (tid == 0) {
        __threadfence();
        atomicAdd(&g_cnt[blockIdx.y], 1u);
        unsigned target = gridDim.x;
        unsigned v;
        do {
            asm volatile("ld.acquire.gpu.global.u32 %0, [%1];"
                         : "=r"(v) : "l"(&g_cnt[blockIdx.y]));
        } while (v < target);
    }
    __syncthreads();

    // ---- epilogue phase 3: quantize register tile -> d_out ----
    float* outq = reinterpret_cast<float*>(d_out);
    const long long qelems = R * (long long)K;
#pragma unroll
    for (int mi = 0; mi < 4; mi++) {
#pragma unroll
        for (int half = 0; half < 2; half++) {
            int r = m0 + wm * 64 + mi * 16 + half * 8 + g;
            unsigned ab;
            asm volatile("ld.global.cg.u32 %0, [%1];"
                         : "=r"(ab) : "l"(&g_absmax[r]));
            const float amax = __uint_as_float(ab);
            const float scale = amax / 127.0f;
            const float inv = (scale == 0.0f) ? 1.0f : (1.0f / scale);
            float* qrow = outq + (size_t)r * K + n0 + wn * 64;
#pragma unroll
            for (int ni = 0; ni < 8; ni++) {
                float q0 = rintf(d[mi][ni][half * 2 + 0] * inv);
                float q1 = rintf(d[mi][ni][half * 2 + 1] * inv);
                q0 = fminf(fmaxf(q0, -127.0f), 127.0f);
                q1 = fminf(fmaxf(q1, -127.0f), 127.0f);
                *reinterpret_cast<float2*>(qrow + ni * 8 + tc) =
                    make_float2(q0, q1);
            }
        }
    }
    if (blockIdx.x == 0) {
        int r = m0 + tid;
        unsigned ab;
        asm volatile("ld.global.cg.u32 %0, [%1];"
                     : "=r"(ab) : "l"(&g_absmax[r]));
        outq[qelems + r] = __uint_as_float(ab) / 127.0f;
    }
}

// ============================================================================
// quantize fallback for modes 1/2
// ============================================================================
__global__ void __launch_bounds__(256) quant_kernel(void* __restrict__ d_out,
                                                    int K, long long R, int mode) {
    const int r = blockIdx.x;
    const int tid = threadIdx.x;
    const float amax = __uint_as_float(g_absmax[r]);
    const float scale = amax / 127.0f;
    const float safe = (scale == 0.0f) ? 1.0f : scale;
    const float inv = 1.0f / safe;

    const float4* yrow = reinterpret_cast<const float4*>(g_y + (size_t)r * K);
    const long long qelems = R * (long long)K;

    for (int i = tid; i < K / 4; i += 256) {
        float4 v = yrow[i];
        float vals[4] = {v.x, v.y, v.z, v.w};
        int q[4];
#pragma unroll
        for (int j = 0; j < 4; j++) {
            float t = rintf(vals[j] * inv);
            q[j] = (int)fminf(fmaxf(t, -127.0f), 127.0f);
        }
        uint32_t p = (uint32_t)(q[0] & 0xFF) | ((uint32_t)(q[1] & 0xFF) << 8) |
                     ((uint32_t)(q[2] & 0xFF) << 16) | ((uint32_t)(q[3] & 0xFF) << 24);
        reinterpret_cast<uint32_t*>(
            reinterpret_cast<char*>(d_out) + (size_t)r * K)[i] = p;
    }
    if (tid == 0 && mode == 1) {
        float* sc = reinterpret_cast<float*>(
            reinterpret_cast<char*>(d_out) + qelems);
        sc[r] = scale;
    }
}

// ============================================================================
// launcher (graph-capture clean)
// ============================================================================
static int isqrt_ll(long long v) {
    long long r = (long long)sqrt((double)v);
    while (r * r > v) r--;
    while ((r + 1) * (r + 1) <= v) r++;
    return (int)r;
}

extern "C" void kernel_launch(void* const* d_in, const int* in_sizes, int n_in,
                              void* d_out, int out_size) {
    long long s0 = in_sizes[0], s1 = (n_in > 1) ? in_sizes[1] : 0;
    const void* xv; const void* hv;
    long long numel_x, numel_h;
    if (s0 >= s1) { xv = d_in[0]; numel_x = s0; hv = d_in[1]; numel_h = s1; }
    else          { xv = d_in[1]; numel_x = s1; hv = d_in[0]; numel_h = s0; }
    const int K = isqrt_ll(numel_h);        // 2048
    const long long R = numel_x / K;        // 32768
    const long long qelems = R * (long long)K;

    int mode;
    if ((long long)out_size == qelems + R)            mode = 0;
    else if ((long long)out_size == qelems + 4LL * R) mode = 1;
    else                                              mode = 2;

    cudaFuncSetAttribute(gemm_fused_kernel,
                         cudaFuncAttributeMaxDynamicSharedMemorySize, SMEM_TOTAL);

    convert_x_kernel<<<(unsigned)((numel_x / 8 + 255) / 256), 256>>>(
        (const float4*)xv, numel_x / 4, (int)R);
    transpose_h_kernel<<<dim3(K / 32, K / 32), dim3(32, 8)>>>((const float*)hv, K);
    gemm_fused_kernel<<<dim3(K / NT, (unsigned)(R / MT)), THREADS, SMEM_TOTAL>>>(
        d_out, K, R, mode);
    if (mode != 0)
        quant_kernel<<<(unsigned)R, 256>>>(d_out, K, R, mode);
}